// round 1
// baseline (speedup 1.0000x reference)
#include <cuda_runtime.h>

// ---------------------------------------------------------------------------
// StandAloneSelfAttention: 7x7 local attention, B=4, H=W=64, C=128, 8 heads x 16
// Kernel 1: fused QKV projection GEMM (fp32, f32x2-packed FFMA)
// Kernel 2: per-pixel local attention with K/V halo tiles in shared memory
// ---------------------------------------------------------------------------

#define IMG 64
#define CH 128
#define HEADS 8
#define HSIZE 16
#define TILE 16
#define HALO 22          // TILE + 6
#define KD 49            // 7*7
#define NPIX (4*IMG*IMG) // 16384

// scratch for q, k, v  (3 * 16384 * 128 floats = 25.2 MB)
__device__ float g_qkv[3][NPIX * CH];

__device__ __forceinline__ unsigned long long ffma2(unsigned long long a,
                                                    unsigned long long b,
                                                    unsigned long long c) {
    unsigned long long d;
    asm("fma.rn.f32x2 %0, %1, %2, %3;" : "=l"(d) : "l"(a), "l"(b), "l"(c));
    return d;
}
__device__ __forceinline__ unsigned long long pack2(float x) {
    unsigned long long d;
    asm("mov.b64 %0, {%1, %1};" : "=l"(d) : "f"(x));
    return d;
}

// ---------------------------------------------------------------------------
// Kernel 1: out = x @ W + b for W in {Wq, Wk, Wv} (blockIdx.y selects)
// Tile: M=128 pixels x N=128 outputs, K=128. 256 threads (16x16),
// each thread computes 8 m x 8 n (as 4 f32x2 pairs at n = 2*tx + 32*jj).
// ---------------------------------------------------------------------------
__global__ __launch_bounds__(256) void qkv_kernel(
    const float* __restrict__ x,
    const float* __restrict__ Wq, const float* __restrict__ bq,
    const float* __restrict__ Wk, const float* __restrict__ bk,
    const float* __restrict__ Wv, const float* __restrict__ bv)
{
    extern __shared__ float sm[];
    float* x_s = sm;            // [128][128] pixel-major
    float* w_s = sm + 128 * 128; // [128][128] k-major

    const int tid = threadIdx.x;
    const int m0 = blockIdx.x * 128;
    const int w = blockIdx.y;
    const float* W = (w == 0) ? Wq : (w == 1) ? Wk : Wv;
    const float* B = (w == 0) ? bq : (w == 1) ? bk : bv;
    float* out = g_qkv[w];

    // load tiles: gmem reads coalesced, smem writes conflict-free
    #pragma unroll
    for (int idx = tid; idx < 128 * 128; idx += 256) {
        int m = idx >> 7, k = idx & 127;
        x_s[idx] = x[(m0 + m) * CH + k];
        w_s[idx] = W[idx];        // W[k][n] row-major
    }
    __syncthreads();

    const int tx = tid & 15;
    const int ty = tid >> 4;
    const int mb = ty * 8;

    unsigned long long acc[8][4];
    #pragma unroll
    for (int i = 0; i < 8; i++)
        #pragma unroll
        for (int jj = 0; jj < 4; jj++) acc[i][jj] = 0ULL;

    #pragma unroll 4
    for (int k = 0; k < 128; k++) {
        unsigned long long bv_[4];
        #pragma unroll
        for (int jj = 0; jj < 4; jj++)
            bv_[jj] = *reinterpret_cast<const unsigned long long*>(
                &w_s[k * 128 + 2 * tx + 32 * jj]);   // conflict-free LDS.64
        #pragma unroll
        for (int i = 0; i < 8; i++) {
            unsigned long long av = pack2(x_s[(mb + i) * 128 + k]); // broadcast
            #pragma unroll
            for (int jj = 0; jj < 4; jj++)
                acc[i][jj] = ffma2(av, bv_[jj], acc[i][jj]);
        }
    }

    #pragma unroll
    for (int i = 0; i < 8; i++) {
        int gm = m0 + mb + i;
        #pragma unroll
        for (int jj = 0; jj < 4; jj++) {
            int n = 2 * tx + 32 * jj;
            float lo, hi;
            asm("mov.b64 {%0,%1}, %2;" : "=f"(lo), "=f"(hi) : "l"(acc[i][jj]));
            float2 r;
            r.x = lo + B[n];
            r.y = hi + B[n + 1];
            *reinterpret_cast<float2*>(&out[gm * CH + n]) = r;
        }
    }
}

// ---------------------------------------------------------------------------
// Kernel 2: local attention. Block = (16x16 pixel tile, head, batch).
// K/V halo (22x22 x 16 dims) staged in smem as 4 float4 planes indexed by
// halo position -> consecutive lanes read consecutive 16B (conflict-free).
// Zero-padded halo entries match reference zero 'SAME' padding semantics.
// ---------------------------------------------------------------------------
__global__ __launch_bounds__(256, 2) void attn_kernel(
    float* __restrict__ out,
    const float* __restrict__ emb0,   // [64, 7, 1]
    const float* __restrict__ emb1)   // [64, 1, 7]
{
    extern __shared__ float4 sm4[];
    float4* k4 = sm4;                 // [4][484]
    float4* v4 = sm4 + 4 * 484;       // [4][484]
    float4* e4 = sm4 + 8 * 484;       // [4][49]

    const int tid = threadIdx.x;
    const int head = blockIdx.y;
    const int b = blockIdx.z;
    const int y0 = (blockIdx.x >> 2) * TILE;
    const int x0 = (blockIdx.x & 3) * TILE;

    const float* gq = g_qkv[0];
    const float* gk = g_qkv[1];
    const float* gv = g_qkv[2];

    // --- load K/V halo into smem planes ---
    for (int i = tid; i < HALO * HALO; i += 256) {
        int hy = i / HALO, hx = i % HALO;
        int gy = y0 + hy - 3, gx = x0 + hx - 3;
        float4 kk[4], vv[4];
        if ((unsigned)gy < (unsigned)IMG && (unsigned)gx < (unsigned)IMG) {
            long off = (((long)(b * IMG + gy) * IMG + gx) * CH + head * HSIZE);
            const float4* kp = reinterpret_cast<const float4*>(gk + off);
            const float4* vp = reinterpret_cast<const float4*>(gv + off);
            #pragma unroll
            for (int j = 0; j < 4; j++) { kk[j] = kp[j]; vv[j] = vp[j]; }
        } else {
            #pragma unroll
            for (int j = 0; j < 4; j++) {
                kk[j] = make_float4(0.f, 0.f, 0.f, 0.f);
                vv[j] = kk[j];
            }
        }
        #pragma unroll
        for (int j = 0; j < 4; j++) {
            k4[j * 484 + i] = kk[j];
            v4[j * 484 + i] = vv[j];
        }
    }

    // --- build emb[head][d][kk] slice: c = head*16+d; c<64 from emb0[c][ki],
    //     else emb1[c-64][kj]  (kk = ki*7 + kj) ---
    for (int idx = tid; idx < HSIZE * KD; idx += 256) {
        int kk = idx % KD;
        int d = idx / KD;
        int ki = kk / 7, kj = kk % 7;
        int c = head * HSIZE + d;
        float val = (c < 64) ? emb0[c * 7 + ki] : emb1[(c - 64) * 7 + kj];
        reinterpret_cast<float*>(e4)[((d >> 2) * KD + kk) * 4 + (d & 3)] = val;
    }
    __syncthreads();

    const int px = tid & 15, py = tid >> 4;
    const int gy = y0 + py, gx = x0 + px;
    const long poff = (((long)(b * IMG + gy) * IMG + gx) * CH + head * HSIZE);

    float4 q[4];
    #pragma unroll
    for (int j = 0; j < 4; j++)
        q[j] = reinterpret_cast<const float4*>(gq + poff)[j];

    // --- scores: s[kk] = q . (k_halo + emb) ---
    float s[KD];
    #pragma unroll
    for (int kk = 0; kk < KD; kk++) {
        int ki = kk / 7, kj = kk % 7;
        int pos = (py + ki) * HALO + px + kj;
        float acc = 0.f;
        #pragma unroll
        for (int j = 0; j < 4; j++) {
            float4 kv = k4[j * 484 + pos];
            float4 ev = e4[j * KD + kk];     // broadcast load
            acc += q[j].x * (kv.x + ev.x);
            acc += q[j].y * (kv.y + ev.y);
            acc += q[j].z * (kv.z + ev.z);
            acc += q[j].w * (kv.w + ev.w);
        }
        s[kk] = acc;
    }

    // --- softmax over the 49 window positions ---
    float mx = s[0];
    #pragma unroll
    for (int kk = 1; kk < KD; kk++) mx = fmaxf(mx, s[kk]);
    float sum = 0.f;
    #pragma unroll
    for (int kk = 0; kk < KD; kk++) {
        float p = __expf(s[kk] - mx);
        s[kk] = p;
        sum += p;
    }
    float inv = 1.f / sum;

    // --- out = (attn @ V) * inv ---
    float4 o[4];
    #pragma unroll
    for (int j = 0; j < 4; j++) o[j] = make_float4(0.f, 0.f, 0.f, 0.f);
    #pragma unroll
    for (int kk = 0; kk < KD; kk++) {
        int ki = kk / 7, kj = kk % 7;
        int pos = (py + ki) * HALO + px + kj;
        float w = s[kk];
        #pragma unroll
        for (int j = 0; j < 4; j++) {
            float4 vv = v4[j * 484 + pos];
            o[j].x += w * vv.x;
            o[j].y += w * vv.y;
            o[j].z += w * vv.z;
            o[j].w += w * vv.w;
        }
    }
    float* op = out + poff;
    #pragma unroll
    for (int j = 0; j < 4; j++) {
        float4 r;
        r.x = o[j].x * inv; r.y = o[j].y * inv;
        r.z = o[j].z * inv; r.w = o[j].w * inv;
        reinterpret_cast<float4*>(op)[j] = r;
    }
}

// ---------------------------------------------------------------------------
extern "C" void kernel_launch(void* const* d_in, const int* in_sizes, int n_in,
                              void* d_out, int out_size)
{
    const float* x  = (const float*)d_in[0];
    const float* Wq = (const float*)d_in[1];
    const float* bq = (const float*)d_in[2];
    const float* Wk = (const float*)d_in[3];
    const float* bk = (const float*)d_in[4];
    const float* Wv = (const float*)d_in[5];
    const float* bv = (const float*)d_in[6];
    const float* e0 = (const float*)d_in[7];
    const float* e1 = (const float*)d_in[8];
    float* out = (float*)d_out;

    const int smem_qkv = 128 * 1024;                    // 2 * 64KB tiles
    const int smem_attn = (8 * 484 + 4 * KD) * 16;      // 65088 B

    cudaFuncSetAttribute(qkv_kernel,
        cudaFuncAttributeMaxDynamicSharedMemorySize, smem_qkv);
    cudaFuncSetAttribute(attn_kernel,
        cudaFuncAttributeMaxDynamicSharedMemorySize, smem_attn);

    qkv_kernel<<<dim3(NPIX / 128, 3), 256, smem_qkv>>>(x, Wq, bq, Wk, bk, Wv, bv);
    attn_kernel<<<dim3(16, HEADS, 4), 256, smem_attn>>>(out, e0, e1);
}